// round 2
// baseline (speedup 1.0000x reference)
#include <cuda_runtime.h>
#include <cstdint>

#define NN   100000
#define HD   64
#define EMAX 3200000

// ---- scratch (device globals; no allocation allowed) ----
__device__ __align__(16) float g_h[NN * HD];     // node features (25.6 MB)
__device__ __align__(16) float g_agg[NN * HD];   // aggregated neighbor features
__device__ int   g_cnt[NN];                      // in-degree
__device__ float g_inv[NN];                      // 1/max(deg,1)
__device__ int   g_rowptr[NN + 1];               // CSR row pointers (by dst)
__device__ int   g_fill[NN];                     // fill cursors for counting sort
__device__ int   g_esrc[EMAX];                   // src ids sorted by dst
__device__ int   g_is64;                         // edge_index dtype flag

// ---------------------------------------------------------------- dtype probe
// int64 node ids < 1e5 => high 32-bit words are all zero. For genuine int32
// data, 64 consecutive odd positions all being zero has probability ~0.
__global__ void detect_kernel(const int* __restrict__ ei32) {
    if (threadIdx.x == 0 && blockIdx.x == 0) {
        int nz = 0;
        for (int k = 0; k < 64; k++) nz |= ei32[2 * k + 1];
        g_is64 = (nz == 0) ? 1 : 0;
    }
}

__device__ __forceinline__ int load_idx(const void* ei, size_t pos) {
    if (g_is64) return (int)((const long long*)ei)[pos];
    return ((const int*)ei)[pos];
}

// ---------------------------------------------------------------- zero
__global__ void zero_kernel() {
    int i = blockIdx.x * blockDim.x + threadIdx.x;
    if (i < NN) { g_cnt[i] = 0; g_fill[i] = 0; }
}

// ---------------------------------------------------------------- degree
__global__ void degree_kernel(const void* __restrict__ ei, int E) {
    int e = blockIdx.x * blockDim.x + threadIdx.x;
    if (e < E) {
        int d = load_idx(ei, (size_t)E + e);   // edge_index[1][e]
        if ((unsigned)d < NN) atomicAdd(&g_cnt[d], 1);
    }
}

// ---------------------------------------------------------------- scan (1 block)
__global__ void scan_kernel() {
    __shared__ int s[1024];
    int tid = threadIdx.x;
    int running = 0;
    if (tid == 0) g_rowptr[0] = 0;
    for (int base = 0; base < NN; base += 1024) {
        int i = base + tid;
        int v = (i < NN) ? g_cnt[i] : 0;
        s[tid] = v;
        __syncthreads();
        for (int off = 1; off < 1024; off <<= 1) {
            int t = (tid >= off) ? s[tid - off] : 0;
            __syncthreads();
            s[tid] += t;
            __syncthreads();
        }
        if (i < NN) g_rowptr[i + 1] = running + s[tid];
        running += s[1023];
        __syncthreads();
    }
}

// ---------------------------------------------------------------- inv degree
__global__ void inv_kernel() {
    int i = blockIdx.x * blockDim.x + threadIdx.x;
    if (i < NN) g_inv[i] = 1.0f / fmaxf((float)g_cnt[i], 1.0f);
}

// ---------------------------------------------------------------- counting-sort scatter
__global__ void scatter_kernel(const void* __restrict__ ei, int E) {
    int e = blockIdx.x * blockDim.x + threadIdx.x;
    if (e < E) {
        int srcv = load_idx(ei, (size_t)e);
        int d    = load_idx(ei, (size_t)E + e);
        if ((unsigned)d < NN && (unsigned)srcv < NN) {
            int pos = g_rowptr[d] + atomicAdd(&g_fill[d], 1);
            if ((unsigned)pos < EMAX) g_esrc[pos] = srcv;
        }
    }
}

// ---------------------------------------------------------------- aggregate (warp per node)
__global__ __launch_bounds__(256) void aggregate_kernel() {
    int gtid = blockIdx.x * blockDim.x + threadIdx.x;
    int w = gtid >> 5, lane = gtid & 31;
    if (w >= NN) return;
    int beg = g_rowptr[w], end = g_rowptr[w + 1];
    float2 acc = make_float2(0.f, 0.f);
    int j = beg;
    while (j < end) {
        int jl = j + lane;
        int sidx = (jl < end) ? g_esrc[jl] : 0;
        int m = end - j; if (m > 32) m = 32;
        for (int t = 0; t < m; t++) {
            int sv = __shfl_sync(0xffffffffu, sidx, t);
            float2 v = *(const float2*)(g_h + (size_t)sv * HD + lane * 2);
            acc.x += v.x; acc.y += v.y;
        }
        j += 32;
    }
    float inv = g_inv[w];
    acc.x *= inv; acc.y *= inv;
    *(float2*)(g_agg + (size_t)w * HD + lane * 2) = acc;
}

// ---------------------------------------------------------------- input GEMM: h = x @ Win + b_in
__global__ __launch_bounds__(256) void gemm_in_kernel(const float* __restrict__ x,
                                                      const float* __restrict__ Win,
                                                      const float* __restrict__ bin) {
    __shared__ __align__(16) float As[32][65];   // [k][m], padded
    __shared__ __align__(16) float Bs[32][64];   // [k][n]
    int tid = threadIdx.x;
    int tx = tid & 15, ty = tid >> 4;
    int row0 = blockIdx.x * 64;
    float acc[4][4];
#pragma unroll
    for (int i = 0; i < 4; i++)
#pragma unroll
        for (int j = 0; j < 4; j++) acc[i][j] = 0.f;

    for (int kc = 0; kc < 512; kc += 32) {
#pragma unroll
        for (int i = 0; i < 2; i++) {
            int idx = tid + i * 256;          // 0..511
            int r = idx >> 3, c4 = idx & 7;   // 64 rows x 8 float4
            int grow = row0 + r;
            float4 v = make_float4(0.f, 0.f, 0.f, 0.f);
            if (grow < NN) v = *(const float4*)(x + (size_t)grow * 512 + kc + c4 * 4);
            As[c4 * 4 + 0][r] = v.x; As[c4 * 4 + 1][r] = v.y;
            As[c4 * 4 + 2][r] = v.z; As[c4 * 4 + 3][r] = v.w;
        }
#pragma unroll
        for (int i = 0; i < 2; i++) {
            int idx = tid + i * 256;
            int r = idx >> 4, c4 = idx & 15;  // 32 rows x 16 float4
            *(float4*)&Bs[r][c4 * 4] = *(const float4*)(Win + (size_t)(kc + r) * 64 + c4 * 4);
        }
        __syncthreads();
#pragma unroll
        for (int k = 0; k < 32; k++) {
            float a[4];
#pragma unroll
            for (int i = 0; i < 4; i++) a[i] = As[k][ty * 4 + i];
            float4 b = *(float4*)&Bs[k][tx * 4];
            float bb[4] = {b.x, b.y, b.z, b.w};
#pragma unroll
            for (int i = 0; i < 4; i++)
#pragma unroll
                for (int j = 0; j < 4; j++) acc[i][j] = fmaf(a[i], bb[j], acc[i][j]);
        }
        __syncthreads();
    }
    float4 bv = *(const float4*)(bin + tx * 4);
#pragma unroll
    for (int i = 0; i < 4; i++) {
        int grow = row0 + ty * 4 + i;
        if (grow < NN) {
            float4 o;
            o.x = acc[i][0] + bv.x; o.y = acc[i][1] + bv.y;
            o.z = acc[i][2] + bv.z; o.w = acc[i][3] + bv.w;
            *(float4*)(g_h + (size_t)grow * 64 + tx * 4) = o;
        }
    }
}

// ---------------------------------------------------------------- fused layer GEMM:
// h = h + relu(agg @ Wl + bl + h @ Wr)
__global__ __launch_bounds__(256) void gemm_layer_kernel(const float* __restrict__ Wl,
                                                         const float* __restrict__ Wr,
                                                         const float* __restrict__ bl) {
    __shared__ __align__(16) float A1s[32][65];
    __shared__ __align__(16) float A2s[32][65];
    __shared__ __align__(16) float Bls[32][64];
    __shared__ __align__(16) float Brs[32][64];
    int tid = threadIdx.x;
    int tx = tid & 15, ty = tid >> 4;
    int row0 = blockIdx.x * 64;
    float acc[4][4];
#pragma unroll
    for (int i = 0; i < 4; i++)
#pragma unroll
        for (int j = 0; j < 4; j++) acc[i][j] = 0.f;

    for (int kc = 0; kc < 64; kc += 32) {
#pragma unroll
        for (int i = 0; i < 2; i++) {
            int idx = tid + i * 256;
            int r = idx >> 3, c4 = idx & 7;
            int grow = row0 + r;
            float4 v1 = make_float4(0.f, 0.f, 0.f, 0.f);
            float4 v2 = v1;
            if (grow < NN) {
                v1 = *(const float4*)(g_agg + (size_t)grow * 64 + kc + c4 * 4);
                v2 = *(const float4*)(g_h  + (size_t)grow * 64 + kc + c4 * 4);
            }
            A1s[c4 * 4 + 0][r] = v1.x; A1s[c4 * 4 + 1][r] = v1.y;
            A1s[c4 * 4 + 2][r] = v1.z; A1s[c4 * 4 + 3][r] = v1.w;
            A2s[c4 * 4 + 0][r] = v2.x; A2s[c4 * 4 + 1][r] = v2.y;
            A2s[c4 * 4 + 2][r] = v2.z; A2s[c4 * 4 + 3][r] = v2.w;
        }
#pragma unroll
        for (int i = 0; i < 2; i++) {
            int idx = tid + i * 256;
            int r = idx >> 4, c4 = idx & 15;
            *(float4*)&Bls[r][c4 * 4] = *(const float4*)(Wl + (size_t)(kc + r) * 64 + c4 * 4);
            *(float4*)&Brs[r][c4 * 4] = *(const float4*)(Wr + (size_t)(kc + r) * 64 + c4 * 4);
        }
        __syncthreads();
#pragma unroll
        for (int k = 0; k < 32; k++) {
            float a1[4], a2[4];
#pragma unroll
            for (int i = 0; i < 4; i++) { a1[i] = A1s[k][ty * 4 + i]; a2[i] = A2s[k][ty * 4 + i]; }
            float4 b1 = *(float4*)&Bls[k][tx * 4];
            float4 b2 = *(float4*)&Brs[k][tx * 4];
            float w1[4] = {b1.x, b1.y, b1.z, b1.w};
            float w2[4] = {b2.x, b2.y, b2.z, b2.w};
#pragma unroll
            for (int i = 0; i < 4; i++)
#pragma unroll
                for (int j = 0; j < 4; j++) {
                    acc[i][j] = fmaf(a1[i], w1[j], acc[i][j]);
                    acc[i][j] = fmaf(a2[i], w2[j], acc[i][j]);
                }
        }
        __syncthreads();
    }
    float4 bb = *(const float4*)(bl + tx * 4);
    float bbv[4] = {bb.x, bb.y, bb.z, bb.w};
#pragma unroll
    for (int i = 0; i < 4; i++) {
        int grow = row0 + ty * 4 + i;
        if (grow < NN) {
            float4 h4 = *(const float4*)(g_h + (size_t)grow * 64 + tx * 4);
            float hv[4] = {h4.x, h4.y, h4.z, h4.w};
            float o[4];
#pragma unroll
            for (int j = 0; j < 4; j++) {
                float c = acc[i][j] + bbv[j];
                o[j] = hv[j] + fmaxf(c, 0.f);
            }
            float4 ov = make_float4(o[0], o[1], o[2], o[3]);
            *(float4*)(g_h + (size_t)grow * 64 + tx * 4) = ov;
        }
    }
}

// ---------------------------------------------------------------- output GEMM:
// out = h @ Wout + b_out   (Wout[64,256]); grid.y = 4 column blocks of 64
__global__ __launch_bounds__(256) void gemm_out_kernel(const float* __restrict__ Wout,
                                                       const float* __restrict__ bout,
                                                       float* __restrict__ out) {
    __shared__ __align__(16) float As[64][65];
    __shared__ __align__(16) float Bs[64][64];
    int tid = threadIdx.x;
    int tx = tid & 15, ty = tid >> 4;
    int row0 = blockIdx.x * 64;
    int col0 = blockIdx.y * 64;

#pragma unroll
    for (int i = 0; i < 4; i++) {
        int idx = tid + i * 256;           // 0..1023
        int r = idx >> 4, c4 = idx & 15;   // 64 rows x 16 float4
        int grow = row0 + r;
        float4 v = make_float4(0.f, 0.f, 0.f, 0.f);
        if (grow < NN) v = *(const float4*)(g_h + (size_t)grow * 64 + c4 * 4);
        As[c4 * 4 + 0][r] = v.x; As[c4 * 4 + 1][r] = v.y;
        As[c4 * 4 + 2][r] = v.z; As[c4 * 4 + 3][r] = v.w;
    }
#pragma unroll
    for (int i = 0; i < 4; i++) {
        int idx = tid + i * 256;
        int r = idx >> 4, c4 = idx & 15;
        *(float4*)&Bs[r][c4 * 4] = *(const float4*)(Wout + (size_t)r * 256 + col0 + c4 * 4);
    }
    __syncthreads();

    float acc[4][4];
#pragma unroll
    for (int i = 0; i < 4; i++)
#pragma unroll
        for (int j = 0; j < 4; j++) acc[i][j] = 0.f;
#pragma unroll
    for (int k = 0; k < 64; k++) {
        float a[4];
#pragma unroll
        for (int i = 0; i < 4; i++) a[i] = As[k][ty * 4 + i];
        float4 b = *(float4*)&Bs[k][tx * 4];
        float bb[4] = {b.x, b.y, b.z, b.w};
#pragma unroll
        for (int i = 0; i < 4; i++)
#pragma unroll
            for (int j = 0; j < 4; j++) acc[i][j] = fmaf(a[i], bb[j], acc[i][j]);
    }
    float4 bv = *(const float4*)(bout + col0 + tx * 4);
#pragma unroll
    for (int i = 0; i < 4; i++) {
        int grow = row0 + ty * 4 + i;
        if (grow < NN) {
            float4 o;
            o.x = acc[i][0] + bv.x; o.y = acc[i][1] + bv.y;
            o.z = acc[i][2] + bv.z; o.w = acc[i][3] + bv.w;
            *(float4*)(out + (size_t)grow * 256 + col0 + tx * 4) = o;
        }
    }
}

// ---------------------------------------------------------------- launch
extern "C" void kernel_launch(void* const* d_in, const int* in_sizes, int n_in,
                              void* d_out, int out_size) {
    const float* x    = (const float*)d_in[0];
    const void*  ei   = d_in[1];
    const float* Win  = (const float*)d_in[2];
    const float* bin  = (const float*)d_in[3];
    const float* Wl   = (const float*)d_in[4];
    const float* bl   = (const float*)d_in[5];
    const float* Wr   = (const float*)d_in[6];
    const float* Wout = (const float*)d_in[7];
    const float* bout = (const float*)d_in[8];
    float* out = (float*)d_out;
    int E = in_sizes[1] / 2;

    detect_kernel<<<1, 32>>>((const int*)ei);
    zero_kernel<<<(NN + 255) / 256, 256>>>();
    degree_kernel<<<(E + 255) / 256, 256>>>(ei, E);
    scan_kernel<<<1, 1024>>>();
    inv_kernel<<<(NN + 255) / 256, 256>>>();
    scatter_kernel<<<(E + 255) / 256, 256>>>(ei, E);

    gemm_in_kernel<<<(NN + 63) / 64, 256>>>(x, Win, bin);

    for (int i = 0; i < 4; i++) {
        aggregate_kernel<<<(NN * 32 + 255) / 256, 256>>>();
        gemm_layer_kernel<<<(NN + 63) / 64, 256>>>(Wl + i * HD * HD, Wr + i * HD * HD, bl + i * HD);
    }

    gemm_out_kernel<<<dim3((NN + 63) / 64, 4), 256>>>(Wout, bout, out);
}

// round 3
// speedup vs baseline: 1.1378x; 1.1378x over previous
#include <cuda_runtime.h>
#include <cuda_fp16.h>
#include <cstdint>

#define NN   100000
#define HD   64
#define EMAX 3200000
#define NBLK ((NN + 1023) / 1024)   // 98

// ---- scratch (device globals; no allocation allowed) ----
__device__ __align__(16) float  g_h[NN * HD];     // node features fp32 (25.6 MB)
__device__ __align__(16) __half g_h16[NN * HD];   // fp16 mirror for gather (12.8 MB)
__device__ __align__(16) float  g_agg[NN * HD];   // aggregated neighbor features
__device__ int   g_cnt[NN];                       // in-degree
__device__ float g_inv[NN];                       // 1/max(deg,1)
__device__ int   g_rowptr[NN + 1];                // CSR row pointers (by dst)
__device__ int   g_fill[NN];                      // fill cursors for counting sort
__device__ int   g_esrc[EMAX];                    // src ids sorted by dst
__device__ int   g_is64;                          // edge_index dtype flag
__device__ int   g_bsum[NBLK];                    // per-block scan sums
__device__ int   g_boff[NBLK];                    // exclusive block offsets

// ---------------------------------------------------------------- dtype probe
__global__ void detect_kernel(const int* __restrict__ ei32) {
    if (threadIdx.x == 0 && blockIdx.x == 0) {
        int nz = 0;
        for (int k = 0; k < 64; k++) nz |= ei32[2 * k + 1];
        g_is64 = (nz == 0) ? 1 : 0;
    }
}

__device__ __forceinline__ int load_idx(const void* ei, size_t pos) {
    if (g_is64) return (int)((const long long*)ei)[pos];
    return ((const int*)ei)[pos];
}

// ---------------------------------------------------------------- zero
__global__ void zero_kernel() {
    int i = blockIdx.x * blockDim.x + threadIdx.x;
    if (i < NN) { g_cnt[i] = 0; g_fill[i] = 0; }
}

// ---------------------------------------------------------------- degree
__global__ void degree_kernel(const void* __restrict__ ei, int E) {
    int e = blockIdx.x * blockDim.x + threadIdx.x;
    if (e < E) {
        int d = load_idx(ei, (size_t)E + e);
        if ((unsigned)d < NN) atomicAdd(&g_cnt[d], 1);
    }
}

// ---------------------------------------------------------------- hierarchical scan
// pass 1: per-block inclusive scan of g_cnt into g_rowptr[i+1]; block sums out.
// Also computes g_inv (fused — g_cnt is already in registers).
__global__ __launch_bounds__(1024) void scan_partial_kernel() {
    __shared__ int s[1024];
    int tid = threadIdx.x, b = blockIdx.x;
    int i = b * 1024 + tid;
    int v = (i < NN) ? g_cnt[i] : 0;
    if (i < NN) g_inv[i] = 1.0f / fmaxf((float)v, 1.0f);
    s[tid] = v;
    __syncthreads();
#pragma unroll
    for (int off = 1; off < 1024; off <<= 1) {
        int t = (tid >= off) ? s[tid - off] : 0;
        __syncthreads();
        s[tid] += t;
        __syncthreads();
    }
    if (i < NN) g_rowptr[i + 1] = s[tid];
    if (tid == 1023) g_bsum[b] = s[1023];
    if (i == 0) g_rowptr[0] = 0;
}

// pass 2: scan the 98 block sums (1 block)
__global__ void scan_bsum_kernel() {
    __shared__ int s[128];
    int tid = threadIdx.x;
    int v = (tid < NBLK) ? g_bsum[tid] : 0;
    s[tid] = v;
    __syncthreads();
#pragma unroll
    for (int off = 1; off < 128; off <<= 1) {
        int t = (tid >= off) ? s[tid - off] : 0;
        __syncthreads();
        s[tid] += t;
        __syncthreads();
    }
    if (tid < NBLK) g_boff[tid] = s[tid] - v;   // exclusive
}

// pass 3: add block offsets
__global__ __launch_bounds__(1024) void scan_add_kernel() {
    int i = blockIdx.x * 1024 + threadIdx.x;
    if (i < NN) g_rowptr[i + 1] += g_boff[blockIdx.x];
}

// ---------------------------------------------------------------- counting-sort scatter
__global__ void scatter_kernel(const void* __restrict__ ei, int E) {
    int e = blockIdx.x * blockDim.x + threadIdx.x;
    if (e < E) {
        int srcv = load_idx(ei, (size_t)e);
        int d    = load_idx(ei, (size_t)E + e);
        if ((unsigned)d < NN && (unsigned)srcv < NN) {
            int pos = g_rowptr[d] + atomicAdd(&g_fill[d], 1);
            if ((unsigned)pos < EMAX) g_esrc[pos] = srcv;
        }
    }
}

// ---------------------------------------------------------------- aggregate (warp per node, fp16 gather)
__global__ __launch_bounds__(256) void aggregate_kernel() {
    int gtid = blockIdx.x * blockDim.x + threadIdx.x;
    int w = gtid >> 5, lane = gtid & 31;
    if (w >= NN) return;
    int beg = g_rowptr[w], end = g_rowptr[w + 1];
    const __half2* __restrict__ base = (const __half2*)g_h16;

    float2 a0 = make_float2(0.f, 0.f), a1 = a0, a2 = a0, a3 = a0;
    int n = end - beg;
    int nfull = n & ~31;
    int j = beg;
    for (; j < beg + nfull; j += 32) {
        int sidx = g_esrc[j + lane];
#pragma unroll
        for (int t = 0; t < 32; t += 4) {
            int s0 = __shfl_sync(0xffffffffu, sidx, t + 0);
            int s1 = __shfl_sync(0xffffffffu, sidx, t + 1);
            int s2 = __shfl_sync(0xffffffffu, sidx, t + 2);
            int s3 = __shfl_sync(0xffffffffu, sidx, t + 3);
            float2 v0 = __half22float2(base[(size_t)s0 * 32 + lane]);
            float2 v1 = __half22float2(base[(size_t)s1 * 32 + lane]);
            float2 v2 = __half22float2(base[(size_t)s2 * 32 + lane]);
            float2 v3 = __half22float2(base[(size_t)s3 * 32 + lane]);
            a0.x += v0.x; a0.y += v0.y;
            a1.x += v1.x; a1.y += v1.y;
            a2.x += v2.x; a2.y += v2.y;
            a3.x += v3.x; a3.y += v3.y;
        }
    }
    if (j < end) {
        int jl = j + lane;
        int sidx = (jl < end) ? g_esrc[jl] : 0;
        int m = end - j;
        for (int t = 0; t < m; t++) {
            int sv = __shfl_sync(0xffffffffu, sidx, t);
            float2 v = __half22float2(base[(size_t)sv * 32 + lane]);
            a0.x += v.x; a0.y += v.y;
        }
    }
    float inv = g_inv[w];
    float2 acc;
    acc.x = (a0.x + a1.x + a2.x + a3.x) * inv;
    acc.y = (a0.y + a1.y + a2.y + a3.y) * inv;
    *(float2*)(g_agg + (size_t)w * HD + lane * 2) = acc;
}

// ---------------------------------------------------------------- input GEMM: h = x @ Win + b_in
__global__ __launch_bounds__(256) void gemm_in_kernel(const float* __restrict__ x,
                                                      const float* __restrict__ Win,
                                                      const float* __restrict__ bin) {
    __shared__ __align__(16) float As[32][65];
    __shared__ __align__(16) float Bs[32][64];
    int tid = threadIdx.x;
    int tx = tid & 15, ty = tid >> 4;
    int row0 = blockIdx.x * 64;
    float acc[4][4];
#pragma unroll
    for (int i = 0; i < 4; i++)
#pragma unroll
        for (int j = 0; j < 4; j++) acc[i][j] = 0.f;

    for (int kc = 0; kc < 512; kc += 32) {
#pragma unroll
        for (int i = 0; i < 2; i++) {
            int idx = tid + i * 256;
            int r = idx >> 3, c4 = idx & 7;
            int grow = row0 + r;
            float4 v = make_float4(0.f, 0.f, 0.f, 0.f);
            if (grow < NN) v = *(const float4*)(x + (size_t)grow * 512 + kc + c4 * 4);
            As[c4 * 4 + 0][r] = v.x; As[c4 * 4 + 1][r] = v.y;
            As[c4 * 4 + 2][r] = v.z; As[c4 * 4 + 3][r] = v.w;
        }
#pragma unroll
        for (int i = 0; i < 2; i++) {
            int idx = tid + i * 256;
            int r = idx >> 4, c4 = idx & 15;
            *(float4*)&Bs[r][c4 * 4] = *(const float4*)(Win + (size_t)(kc + r) * 64 + c4 * 4);
        }
        __syncthreads();
#pragma unroll
        for (int k = 0; k < 32; k++) {
            float a[4];
#pragma unroll
            for (int i = 0; i < 4; i++) a[i] = As[k][ty * 4 + i];
            float4 b = *(float4*)&Bs[k][tx * 4];
            float bb[4] = {b.x, b.y, b.z, b.w};
#pragma unroll
            for (int i = 0; i < 4; i++)
#pragma unroll
                for (int j = 0; j < 4; j++) acc[i][j] = fmaf(a[i], bb[j], acc[i][j]);
        }
        __syncthreads();
    }
    float4 bv = *(const float4*)(bin + tx * 4);
#pragma unroll
    for (int i = 0; i < 4; i++) {
        int grow = row0 + ty * 4 + i;
        if (grow < NN) {
            float4 o;
            o.x = acc[i][0] + bv.x; o.y = acc[i][1] + bv.y;
            o.z = acc[i][2] + bv.z; o.w = acc[i][3] + bv.w;
            *(float4*)(g_h + (size_t)grow * 64 + tx * 4) = o;
            __half2* hp = (__half2*)(g_h16 + (size_t)grow * 64 + tx * 4);
            hp[0] = __floats2half2_rn(o.x, o.y);
            hp[1] = __floats2half2_rn(o.z, o.w);
        }
    }
}

// ---------------------------------------------------------------- fused layer GEMM:
// h = h + relu(agg @ Wl + bl + h @ Wr); also refreshes fp16 mirror
__global__ __launch_bounds__(256) void gemm_layer_kernel(const float* __restrict__ Wl,
                                                         const float* __restrict__ Wr,
                                                         const float* __restrict__ bl) {
    __shared__ __align__(16) float A1s[32][65];
    __shared__ __align__(16) float A2s[32][65];
    __shared__ __align__(16) float Bls[32][64];
    __shared__ __align__(16) float Brs[32][64];
    int tid = threadIdx.x;
    int tx = tid & 15, ty = tid >> 4;
    int row0 = blockIdx.x * 64;
    float acc[4][4];
#pragma unroll
    for (int i = 0; i < 4; i++)
#pragma unroll
        for (int j = 0; j < 4; j++) acc[i][j] = 0.f;

    for (int kc = 0; kc < 64; kc += 32) {
#pragma unroll
        for (int i = 0; i < 2; i++) {
            int idx = tid + i * 256;
            int r = idx >> 3, c4 = idx & 7;
            int grow = row0 + r;
            float4 v1 = make_float4(0.f, 0.f, 0.f, 0.f);
            float4 v2 = v1;
            if (grow < NN) {
                v1 = *(const float4*)(g_agg + (size_t)grow * 64 + kc + c4 * 4);
                v2 = *(const float4*)(g_h  + (size_t)grow * 64 + kc + c4 * 4);
            }
            A1s[c4 * 4 + 0][r] = v1.x; A1s[c4 * 4 + 1][r] = v1.y;
            A1s[c4 * 4 + 2][r] = v1.z; A1s[c4 * 4 + 3][r] = v1.w;
            A2s[c4 * 4 + 0][r] = v2.x; A2s[c4 * 4 + 1][r] = v2.y;
            A2s[c4 * 4 + 2][r] = v2.z; A2s[c4 * 4 + 3][r] = v2.w;
        }
#pragma unroll
        for (int i = 0; i < 2; i++) {
            int idx = tid + i * 256;
            int r = idx >> 4, c4 = idx & 15;
            *(float4*)&Bls[r][c4 * 4] = *(const float4*)(Wl + (size_t)(kc + r) * 64 + c4 * 4);
            *(float4*)&Brs[r][c4 * 4] = *(const float4*)(Wr + (size_t)(kc + r) * 64 + c4 * 4);
        }
        __syncthreads();
#pragma unroll
        for (int k = 0; k < 32; k++) {
            float a1[4], a2[4];
#pragma unroll
            for (int i = 0; i < 4; i++) { a1[i] = A1s[k][ty * 4 + i]; a2[i] = A2s[k][ty * 4 + i]; }
            float4 b1 = *(float4*)&Bls[k][tx * 4];
            float4 b2 = *(float4*)&Brs[k][tx * 4];
            float w1[4] = {b1.x, b1.y, b1.z, b1.w};
            float w2[4] = {b2.x, b2.y, b2.z, b2.w};
#pragma unroll
            for (int i = 0; i < 4; i++)
#pragma unroll
                for (int j = 0; j < 4; j++) {
                    acc[i][j] = fmaf(a1[i], w1[j], acc[i][j]);
                    acc[i][j] = fmaf(a2[i], w2[j], acc[i][j]);
                }
        }
        __syncthreads();
    }
    float4 bb = *(const float4*)(bl + tx * 4);
    float bbv[4] = {bb.x, bb.y, bb.z, bb.w};
#pragma unroll
    for (int i = 0; i < 4; i++) {
        int grow = row0 + ty * 4 + i;
        if (grow < NN) {
            float4 h4 = *(const float4*)(g_h + (size_t)grow * 64 + tx * 4);
            float hv[4] = {h4.x, h4.y, h4.z, h4.w};
            float o[4];
#pragma unroll
            for (int j = 0; j < 4; j++) {
                float c = acc[i][j] + bbv[j];
                o[j] = hv[j] + fmaxf(c, 0.f);
            }
            float4 ov = make_float4(o[0], o[1], o[2], o[3]);
            *(float4*)(g_h + (size_t)grow * 64 + tx * 4) = ov;
            __half2* hp = (__half2*)(g_h16 + (size_t)grow * 64 + tx * 4);
            hp[0] = __floats2half2_rn(o[0], o[1]);
            hp[1] = __floats2half2_rn(o[2], o[3]);
        }
    }
}

// ---------------------------------------------------------------- output GEMM
__global__ __launch_bounds__(256) void gemm_out_kernel(const float* __restrict__ Wout,
                                                       const float* __restrict__ bout,
                                                       float* __restrict__ out) {
    __shared__ __align__(16) float As[64][65];
    __shared__ __align__(16) float Bs[64][64];
    int tid = threadIdx.x;
    int tx = tid & 15, ty = tid >> 4;
    int row0 = blockIdx.x * 64;
    int col0 = blockIdx.y * 64;

#pragma unroll
    for (int i = 0; i < 4; i++) {
        int idx = tid + i * 256;
        int r = idx >> 4, c4 = idx & 15;
        int grow = row0 + r;
        float4 v = make_float4(0.f, 0.f, 0.f, 0.f);
        if (grow < NN) v = *(const float4*)(g_h + (size_t)grow * 64 + c4 * 4);
        As[c4 * 4 + 0][r] = v.x; As[c4 * 4 + 1][r] = v.y;
        As[c4 * 4 + 2][r] = v.z; As[c4 * 4 + 3][r] = v.w;
    }
#pragma unroll
    for (int i = 0; i < 4; i++) {
        int idx = tid + i * 256;
        int r = idx >> 4, c4 = idx & 15;
        *(float4*)&Bs[r][c4 * 4] = *(const float4*)(Wout + (size_t)r * 256 + col0 + c4 * 4);
    }
    __syncthreads();

    float acc[4][4];
#pragma unroll
    for (int i = 0; i < 4; i++)
#pragma unroll
        for (int j = 0; j < 4; j++) acc[i][j] = 0.f;
#pragma unroll
    for (int k = 0; k < 64; k++) {
        float a[4];
#pragma unroll
        for (int i = 0; i < 4; i++) a[i] = As[k][ty * 4 + i];
        float4 b = *(float4*)&Bs[k][tx * 4];
        float bb[4] = {b.x, b.y, b.z, b.w};
#pragma unroll
        for (int i = 0; i < 4; i++)
#pragma unroll
            for (int j = 0; j < 4; j++) acc[i][j] = fmaf(a[i], bb[j], acc[i][j]);
    }
    float4 bv = *(const float4*)(bout + col0 + tx * 4);
#pragma unroll
    for (int i = 0; i < 4; i++) {
        int grow = row0 + ty * 4 + i;
        if (grow < NN) {
            float4 o;
            o.x = acc[i][0] + bv.x; o.y = acc[i][1] + bv.y;
            o.z = acc[i][2] + bv.z; o.w = acc[i][3] + bv.w;
            *(float4*)(out + (size_t)grow * 256 + col0 + tx * 4) = o;
        }
    }
}

// ---------------------------------------------------------------- launch
extern "C" void kernel_launch(void* const* d_in, const int* in_sizes, int n_in,
                              void* d_out, int out_size) {
    const float* x    = (const float*)d_in[0];
    const void*  ei   = d_in[1];
    const float* Win  = (const float*)d_in[2];
    const float* bin  = (const float*)d_in[3];
    const float* Wl   = (const float*)d_in[4];
    const float* bl   = (const float*)d_in[5];
    const float* Wr   = (const float*)d_in[6];
    const float* Wout = (const float*)d_in[7];
    const float* bout = (const float*)d_in[8];
    float* out = (float*)d_out;
    int E = in_sizes[1] / 2;

    detect_kernel<<<1, 32>>>((const int*)ei);
    zero_kernel<<<(NN + 255) / 256, 256>>>();
    degree_kernel<<<(E + 255) / 256, 256>>>(ei, E);
    scan_partial_kernel<<<NBLK, 1024>>>();
    scan_bsum_kernel<<<1, 128>>>();
    scan_add_kernel<<<NBLK, 1024>>>();
    scatter_kernel<<<(E + 255) / 256, 256>>>(ei, E);

    gemm_in_kernel<<<(NN + 63) / 64, 256>>>(x, Win, bin);

    for (int i = 0; i < 4; i++) {
        aggregate_kernel<<<(NN * 32 + 255) / 256, 256>>>();
        gemm_layer_kernel<<<(NN + 63) / 64, 256>>>(Wl + i * HD * HD, Wr + i * HD * HD, bl + i * HD);
    }

    gemm_out_kernel<<<dim3((NN + 63) / 64, 4), 256>>>(Wout, bout, out);
}

// round 4
// speedup vs baseline: 1.2677x; 1.1141x over previous
#include <cuda_runtime.h>
#include <cuda_fp16.h>
#include <cstdint>

#define NN   100000
#define HD   64
#define EMAX 3200000
#define NBLK ((NN + 1023) / 1024)   // 98
#define MBLK ((NN + 63) / 64)       // 1563

// ---- scratch (device globals; no allocation allowed) ----
__device__ __align__(16) float  g_h[NN * HD];     // node features fp32 (25.6 MB)
__device__ __align__(16) __half g_h16[NN * HD];   // fp16 mirror for gather (12.8 MB)
__device__ __align__(16) float  g_agg[NN * HD];   // aggregated neighbor features
__device__ int   g_cnt[NN];
__device__ float g_inv[NN];
__device__ int   g_rowptr[NN + 1];
__device__ int   g_fill[NN];
__device__ int   g_esrc[EMAX];
__device__ int   g_is64;
__device__ int   g_bsum[NBLK];
__device__ int   g_boff[NBLK];

// ---------------------------------------------------------------- mma helpers
__device__ __forceinline__ uint32_t cvt_tf32(float x) {
    uint32_t r; asm("cvt.rna.tf32.f32 %0, %1;" : "=r"(r) : "f"(x)); return r;
}
__device__ __forceinline__ void split_tf32(float x, uint32_t& hi, uint32_t& lo) {
    hi = cvt_tf32(x);
    lo = cvt_tf32(x - __uint_as_float(hi));
}
__device__ __forceinline__ void mma_tf32(float* d, const uint32_t* a, const uint32_t* b) {
    asm volatile(
        "mma.sync.aligned.m16n8k8.row.col.f32.tf32.tf32.f32 "
        "{%0,%1,%2,%3}, {%4,%5,%6,%7}, {%8,%9}, {%0,%1,%2,%3};\n"
        : "+f"(d[0]), "+f"(d[1]), "+f"(d[2]), "+f"(d[3])
        : "r"(a[0]), "r"(a[1]), "r"(a[2]), "r"(a[3]), "r"(b[0]), "r"(b[1]));
}

// ---------------------------------------------------------------- dtype probe
__global__ void detect_kernel(const int* __restrict__ ei32) {
    if (threadIdx.x == 0 && blockIdx.x == 0) {
        int nz = 0;
        for (int k = 0; k < 64; k++) nz |= ei32[2 * k + 1];
        g_is64 = (nz == 0) ? 1 : 0;
    }
}
__device__ __forceinline__ int load_idx(const void* ei, size_t pos) {
    if (g_is64) return (int)((const long long*)ei)[pos];
    return ((const int*)ei)[pos];
}

// ---------------------------------------------------------------- zero / degree
__global__ void zero_kernel() {
    int i = blockIdx.x * blockDim.x + threadIdx.x;
    if (i < NN) { g_cnt[i] = 0; g_fill[i] = 0; }
}
__global__ void degree_kernel(const void* __restrict__ ei, int E) {
    int e = blockIdx.x * blockDim.x + threadIdx.x;
    if (e < E) {
        int d = load_idx(ei, (size_t)E + e);
        if ((unsigned)d < NN) atomicAdd(&g_cnt[d], 1);
    }
}

// ---------------------------------------------------------------- hierarchical scan
__global__ __launch_bounds__(1024) void scan_partial_kernel() {
    __shared__ int s[1024];
    int tid = threadIdx.x, b = blockIdx.x;
    int i = b * 1024 + tid;
    int v = (i < NN) ? g_cnt[i] : 0;
    if (i < NN) g_inv[i] = 1.0f / fmaxf((float)v, 1.0f);
    s[tid] = v;
    __syncthreads();
#pragma unroll
    for (int off = 1; off < 1024; off <<= 1) {
        int t = (tid >= off) ? s[tid - off] : 0;
        __syncthreads();
        s[tid] += t;
        __syncthreads();
    }
    if (i < NN) g_rowptr[i + 1] = s[tid];
    if (tid == 1023) g_bsum[b] = s[1023];
    if (i == 0) g_rowptr[0] = 0;
}
__global__ void scan_bsum_kernel() {
    __shared__ int s[128];
    int tid = threadIdx.x;
    int v = (tid < NBLK) ? g_bsum[tid] : 0;
    s[tid] = v;
    __syncthreads();
#pragma unroll
    for (int off = 1; off < 128; off <<= 1) {
        int t = (tid >= off) ? s[tid - off] : 0;
        __syncthreads();
        s[tid] += t;
        __syncthreads();
    }
    if (tid < NBLK) g_boff[tid] = s[tid] - v;
}
__global__ __launch_bounds__(1024) void scan_add_kernel() {
    int i = blockIdx.x * 1024 + threadIdx.x;
    if (i < NN) g_rowptr[i + 1] += g_boff[blockIdx.x];
}

// ---------------------------------------------------------------- counting-sort scatter
__global__ void scatter_kernel(const void* __restrict__ ei, int E) {
    int e = blockIdx.x * blockDim.x + threadIdx.x;
    if (e < E) {
        int srcv = load_idx(ei, (size_t)e);
        int d    = load_idx(ei, (size_t)E + e);
        if ((unsigned)d < NN && (unsigned)srcv < NN) {
            int pos = g_rowptr[d] + atomicAdd(&g_fill[d], 1);
            if ((unsigned)pos < EMAX) g_esrc[pos] = srcv;
        }
    }
}

// ---------------------------------------------------------------- aggregate (warp per node, fp16 gather)
__global__ __launch_bounds__(256) void aggregate_kernel() {
    int gtid = blockIdx.x * blockDim.x + threadIdx.x;
    int w = gtid >> 5, lane = gtid & 31;
    if (w >= NN) return;
    int beg = g_rowptr[w], end = g_rowptr[w + 1];
    const __half2* __restrict__ base = (const __half2*)g_h16;

    float2 a0 = make_float2(0.f, 0.f), a1 = a0, a2 = a0, a3 = a0;
    int n = end - beg;
    int nfull = n & ~31;
    int j = beg;
    for (; j < beg + nfull; j += 32) {
        int sidx = g_esrc[j + lane];
#pragma unroll
        for (int t = 0; t < 32; t += 4) {
            int s0 = __shfl_sync(0xffffffffu, sidx, t + 0);
            int s1 = __shfl_sync(0xffffffffu, sidx, t + 1);
            int s2 = __shfl_sync(0xffffffffu, sidx, t + 2);
            int s3 = __shfl_sync(0xffffffffu, sidx, t + 3);
            float2 v0 = __half22float2(base[(size_t)s0 * 32 + lane]);
            float2 v1 = __half22float2(base[(size_t)s1 * 32 + lane]);
            float2 v2 = __half22float2(base[(size_t)s2 * 32 + lane]);
            float2 v3 = __half22float2(base[(size_t)s3 * 32 + lane]);
            a0.x += v0.x; a0.y += v0.y;
            a1.x += v1.x; a1.y += v1.y;
            a2.x += v2.x; a2.y += v2.y;
            a3.x += v3.x; a3.y += v3.y;
        }
    }
    if (j < end) {
        int jl = j + lane;
        int sidx = (jl < end) ? g_esrc[jl] : 0;
        int m = end - j;
        for (int t = 0; t < m; t++) {
            int sv = __shfl_sync(0xffffffffu, sidx, t);
            float2 v = __half22float2(base[(size_t)sv * 32 + lane]);
            a0.x += v.x; a0.y += v.y;
        }
    }
    float inv = g_inv[w];
    float2 acc;
    acc.x = (a0.x + a1.x + a2.x + a3.x) * inv;
    acc.y = (a0.y + a1.y + a2.y + a3.y) * inv;
    *(float2*)(g_agg + (size_t)w * HD + lane * 2) = acc;
}

// ================================================================ MMA GEMMs
// Warp layout per 256-thread block: warpM = wid&3 (4 x 16 rows = 64),
// warpN = wid>>2 (2 x 32 cols = 64). m16n8k8 tf32 fragments, 3xTF32 splits.
// Smem pads: A row stride 68 (bank = 4*qrow+qcol, bijective), B row stride 72
// (bank = 8*qcol+qrow, bijective) -> conflict-free fragment reads.

#define AW 68
#define BW 72

// ---- per-k-step fragment compute: loads A frags (rows m0..), B frags, 3 mmas.
__device__ __forceinline__ void mma_kstep(const float* As, const float* Bs,
                                          int m0, int n0, int k0,
                                          int qrow, int qcol,
                                          float acc[4][4]) {
    float af[4];
    af[0] = As[(m0 + qrow) * AW + k0 + qcol];
    af[1] = As[(m0 + qrow + 8) * AW + k0 + qcol];
    af[2] = As[(m0 + qrow) * AW + k0 + qcol + 4];
    af[3] = As[(m0 + qrow + 8) * AW + k0 + qcol + 4];
    uint32_t ah[4], al[4];
#pragma unroll
    for (int i = 0; i < 4; i++) split_tf32(af[i], ah[i], al[i]);
#pragma unroll
    for (int nt = 0; nt < 4; nt++) {
        int nn = n0 + nt * 8;
        float bf0 = Bs[(k0 + qcol) * BW + nn + qrow];
        float bf1 = Bs[(k0 + qcol + 4) * BW + nn + qrow];
        uint32_t bh[2], blo[2];
        split_tf32(bf0, bh[0], blo[0]);
        split_tf32(bf1, bh[1], blo[1]);
        mma_tf32(acc[nt], ah, bh);
        mma_tf32(acc[nt], ah, blo);
        mma_tf32(acc[nt], al, bh);
    }
}

// ---------------------------------------------------------------- input GEMM: h = x @ Win + b_in
__global__ __launch_bounds__(256) void gemm_in_mma(const float* __restrict__ x,
                                                   const float* __restrict__ Win,
                                                   const float* __restrict__ bin) {
    __shared__ __align__(16) float As[64 * AW];
    __shared__ __align__(16) float Bs[64 * BW];
    int tid = threadIdx.x;
    int wid = tid >> 5, lane = tid & 31;
    int warpM = wid & 3, warpN = wid >> 2;
    int qrow = lane >> 2, qcol = lane & 3;
    int row0 = blockIdx.x * 64;
    float acc[4][4];
#pragma unroll
    for (int nt = 0; nt < 4; nt++)
#pragma unroll
        for (int i = 0; i < 4; i++) acc[nt][i] = 0.f;

    for (int kc = 0; kc < 512; kc += 64) {
#pragma unroll
        for (int it = 0; it < 4; it++) {
            int idx = tid + it * 256;            // 0..1023
            int r = idx >> 4, c4 = idx & 15;
            int grow = row0 + r;
            float4 v = make_float4(0.f, 0.f, 0.f, 0.f);
            if (grow < NN) v = *(const float4*)(x + (size_t)grow * 512 + kc + c4 * 4);
            *(float4*)&As[r * AW + c4 * 4] = v;
            *(float4*)&Bs[r * BW + c4 * 4] = *(const float4*)(Win + (size_t)(kc + r) * 64 + c4 * 4);
        }
        __syncthreads();
#pragma unroll
        for (int kk = 0; kk < 8; kk++)
            mma_kstep(As, Bs, warpM * 16, warpN * 32, kk * 8, qrow, qcol, acc);
        __syncthreads();
    }
#pragma unroll
    for (int nt = 0; nt < 4; nt++) {
        int gc = warpN * 32 + nt * 8 + qcol * 2;
        float2 bv = *(const float2*)(bin + gc);
#pragma unroll
        for (int half = 0; half < 2; half++) {
            int gr = row0 + warpM * 16 + qrow + half * 8;
            if (gr < NN) {
                float2 o;
                o.x = acc[nt][half * 2 + 0] + bv.x;
                o.y = acc[nt][half * 2 + 1] + bv.y;
                *(float2*)(g_h + (size_t)gr * 64 + gc) = o;
                *(__half2*)(g_h16 + (size_t)gr * 64 + gc) = __floats2half2_rn(o.x, o.y);
            }
        }
    }
}

// ---------------------------------------------------------------- layer GEMM:
// h = h + relu(agg @ Wl + bl + h @ Wr)  (concatenated K: chunk0=agg/Wl, chunk1=h/Wr)
__global__ __launch_bounds__(256) void gemm_layer_mma(const float* __restrict__ Wl,
                                                      const float* __restrict__ Wr,
                                                      const float* __restrict__ bl) {
    __shared__ __align__(16) float As[64 * AW];
    __shared__ __align__(16) float Bs[64 * BW];
    int tid = threadIdx.x;
    int wid = tid >> 5, lane = tid & 31;
    int warpM = wid & 3, warpN = wid >> 2;
    int qrow = lane >> 2, qcol = lane & 3;
    int row0 = blockIdx.x * 64;
    float acc[4][4];
#pragma unroll
    for (int nt = 0; nt < 4; nt++)
#pragma unroll
        for (int i = 0; i < 4; i++) acc[nt][i] = 0.f;

#pragma unroll
    for (int kc = 0; kc < 2; kc++) {
        const float* Asrc = kc ? g_h : g_agg;
        const float* Bsrc = kc ? Wr : Wl;
#pragma unroll
        for (int it = 0; it < 4; it++) {
            int idx = tid + it * 256;
            int r = idx >> 4, c4 = idx & 15;
            int grow = row0 + r;
            float4 v = make_float4(0.f, 0.f, 0.f, 0.f);
            if (grow < NN) v = *(const float4*)(Asrc + (size_t)grow * 64 + c4 * 4);
            *(float4*)&As[r * AW + c4 * 4] = v;
            *(float4*)&Bs[r * BW + c4 * 4] = *(const float4*)(Bsrc + (size_t)r * 64 + c4 * 4);
        }
        __syncthreads();
#pragma unroll
        for (int kk = 0; kk < 8; kk++)
            mma_kstep(As, Bs, warpM * 16, warpN * 32, kk * 8, qrow, qcol, acc);
        __syncthreads();
    }
#pragma unroll
    for (int nt = 0; nt < 4; nt++) {
        int gc = warpN * 32 + nt * 8 + qcol * 2;
        float2 bv = *(const float2*)(bl + gc);
#pragma unroll
        for (int half = 0; half < 2; half++) {
            int gr = row0 + warpM * 16 + qrow + half * 8;
            if (gr < NN) {
                float2 old = *(const float2*)(g_h + (size_t)gr * 64 + gc);
                float2 o;
                o.x = old.x + fmaxf(acc[nt][half * 2 + 0] + bv.x, 0.f);
                o.y = old.y + fmaxf(acc[nt][half * 2 + 1] + bv.y, 0.f);
                *(float2*)(g_h + (size_t)gr * 64 + gc) = o;
                *(__half2*)(g_h16 + (size_t)gr * 64 + gc) = __floats2half2_rn(o.x, o.y);
            }
        }
    }
}

// ---------------------------------------------------------------- output GEMM: out = h @ Wout + b_out
__global__ __launch_bounds__(256) void gemm_out_mma(const float* __restrict__ Wout,
                                                    const float* __restrict__ bout,
                                                    float* __restrict__ out) {
    __shared__ __align__(16) float As[64 * AW];
    __shared__ __align__(16) float Bs[64 * BW];
    int tid = threadIdx.x;
    int wid = tid >> 5, lane = tid & 31;
    int warpM = wid & 3, warpN = wid >> 2;
    int qrow = lane >> 2, qcol = lane & 3;
    int row0 = blockIdx.x * 64;
    int col0 = blockIdx.y * 64;
    float acc[4][4];
#pragma unroll
    for (int nt = 0; nt < 4; nt++)
#pragma unroll
        for (int i = 0; i < 4; i++) acc[nt][i] = 0.f;

#pragma unroll
    for (int it = 0; it < 4; it++) {
        int idx = tid + it * 256;
        int r = idx >> 4, c4 = idx & 15;
        int grow = row0 + r;
        float4 v = make_float4(0.f, 0.f, 0.f, 0.f);
        if (grow < NN) v = *(const float4*)(g_h + (size_t)grow * 64 + c4 * 4);
        *(float4*)&As[r * AW + c4 * 4] = v;
        *(float4*)&Bs[r * BW + c4 * 4] = *(const float4*)(Wout + (size_t)r * 256 + col0 + c4 * 4);
    }
    __syncthreads();
#pragma unroll
    for (int kk = 0; kk < 8; kk++)
        mma_kstep(As, Bs, warpM * 16, warpN * 32, kk * 8, qrow, qcol, acc);

#pragma unroll
    for (int nt = 0; nt < 4; nt++) {
        int gc = warpN * 32 + nt * 8 + qcol * 2;
        float2 bv = *(const float2*)(bout + col0 + gc);
#pragma unroll
        for (int half = 0; half < 2; half++) {
            int gr = row0 + warpM * 16 + qrow + half * 8;
            if (gr < NN) {
                float2 o;
                o.x = acc[nt][half * 2 + 0] + bv.x;
                o.y = acc[nt][half * 2 + 1] + bv.y;
                *(float2*)(out + (size_t)gr * 256 + col0 + gc) = o;
            }
        }
    }
}

// ---------------------------------------------------------------- launch
extern "C" void kernel_launch(void* const* d_in, const int* in_sizes, int n_in,
                              void* d_out, int out_size) {
    const float* x    = (const float*)d_in[0];
    const void*  ei   = d_in[1];
    const float* Win  = (const float*)d_in[2];
    const float* bin  = (const float*)d_in[3];
    const float* Wl   = (const float*)d_in[4];
    const float* bl   = (const float*)d_in[5];
    const float* Wr   = (const float*)d_in[6];
    const float* Wout = (const float*)d_in[7];
    const float* bout = (const float*)d_in[8];
    float* out = (float*)d_out;
    int E = in_sizes[1] / 2;

    detect_kernel<<<1, 32>>>((const int*)ei);
    zero_kernel<<<(NN + 255) / 256, 256>>>();
    degree_kernel<<<(E + 255) / 256, 256>>>(ei, E);
    scan_partial_kernel<<<NBLK, 1024>>>();
    scan_bsum_kernel<<<1, 128>>>();
    scan_add_kernel<<<NBLK, 1024>>>();
    scatter_kernel<<<(E + 255) / 256, 256>>>(ei, E);

    gemm_in_mma<<<MBLK, 256>>>(x, Win, bin);

    for (int i = 0; i < 4; i++) {
        aggregate_kernel<<<(NN * 32 + 255) / 256, 256>>>();
        gemm_layer_mma<<<MBLK, 256>>>(Wl + i * HD * HD, Wr + i * HD * HD, bl + i * HD);
    }

    gemm_out_mma<<<dim3(MBLK, 4), 256>>>(Wout, bout, out);
}